// round 6
// baseline (speedup 1.0000x reference)
#include <cuda_runtime.h>
#include <cuda_bf16.h>
#include <cstdint>

// Problem constants
#define Stok 16384
#define Mdim 512
#define Edim 16
#define Ddim 256
#define H1d  500
#define H2d  500
#define H3d  1000

// Padded dims (K and N padded to GEMM-friendly sizes, zero-filled)
#define KP1 512
#define NP1 512
#define KP2 512
#define NP2 512
#define KP3 512
#define NP3 1024
#define KP4 1024
#define NP4 256

// Tiling
#define TM 128                       // M rows per CTA tile (expert-padded)
#define NR (2*Stok + Edim*TM)        // 34816 padded assignment rows
#define NT_MAX (2*Stok/TM + Edim)    // 272 tiles max
#define RBLOCKS (Stok/8)             // 2048 router blocks

// -------- scratch (device globals; allocation-free per harness rules) --------
__device__ __nv_bfloat16 g_Xhi[(size_t)Stok*KP1];
__device__ __nv_bfloat16 g_Xlo[(size_t)Stok*KP1];
__device__ __nv_bfloat16 g_A1h[(size_t)NR*NP1];
__device__ __nv_bfloat16 g_A1l[(size_t)NR*NP1];
__device__ __nv_bfloat16 g_A2h[(size_t)NR*NP2];
__device__ __nv_bfloat16 g_A2l[(size_t)NR*NP2];
__device__ __nv_bfloat16 g_A3h[(size_t)NR*NP3];
__device__ __nv_bfloat16 g_A3l[(size_t)NR*NP3];
__device__ float         g_A4[(size_t)NR*NP4];

__device__ __nv_bfloat16 g_W1h[(size_t)Edim*NP1*KP1];
__device__ __nv_bfloat16 g_W1l[(size_t)Edim*NP1*KP1];
__device__ __nv_bfloat16 g_W2h[(size_t)Edim*NP2*KP2];
__device__ __nv_bfloat16 g_W2l[(size_t)Edim*NP2*KP2];
__device__ __nv_bfloat16 g_W3h[(size_t)Edim*NP3*KP3];
__device__ __nv_bfloat16 g_W3l[(size_t)Edim*NP3*KP3];
__device__ __nv_bfloat16 g_W4h[(size_t)Edim*NP4*KP4];
__device__ __nv_bfloat16 g_W4l[(size_t)Edim*NP4*KP4];

__device__ float g_b1p[Edim*NP1];
__device__ float g_b2p[Edim*NP2];
__device__ float g_b3p[Edim*NP3];
__device__ float g_b4p[Edim*NP4];

__device__ int   g_row_token[NR];
__device__ int   g_token_rows[2*Stok];
__device__ float g_gate[2*Stok];
__device__ int   g_topk[2*Stok];
__device__ int   g_counts[Edim];
__device__ int   g_cursor[Edim];
__device__ int   g_offsets[Edim];
__device__ int   g_tile_expert[NT_MAX];
__device__ int   g_tile_row0[NT_MAX];
__device__ int   g_n_tiles;
__device__ float g_proxy_partial[RBLOCKS*Edim];

// ---------------------------------------------------------------------------
__device__ __forceinline__ void split2(float a, float b, uint32_t& hi, uint32_t& lo) {
    __nv_bfloat16 ha = __float2bfloat16(a), hb = __float2bfloat16(b);
    float ra = a - __bfloat162float(ha);
    float rb = b - __bfloat162float(hb);
    __nv_bfloat162 H = __halves2bfloat162(ha, hb);
    __nv_bfloat162 L = __floats2bfloat162_rn(ra, rb);
    hi = *(uint32_t*)&H; lo = *(uint32_t*)&L;
}

__device__ __forceinline__ uint32_t smem_u32(const void* p) {
    uint32_t a;
    asm("{ .reg .u64 t; cvta.to.shared.u64 t, %1; cvt.u32.u64 %0, t; }" : "=r"(a) : "l"(p));
    return a;
}

#define MMA4(d, a, b) \
    asm volatile("mma.sync.aligned.m16n8k16.row.col.f32.bf16.bf16.f32 " \
        "{%0,%1,%2,%3},{%4,%5,%6,%7},{%8,%9},{%0,%1,%2,%3};" \
        : "+f"((d)[0]), "+f"((d)[1]), "+f"((d)[2]), "+f"((d)[3]) \
        : "r"((a)[0]), "r"((a)[1]), "r"((a)[2]), "r"((a)[3]), "r"((b)[0]), "r"((b)[1]))

#define LDSM4(d0,d1,d2,d3,a) \
    asm volatile("ldmatrix.sync.aligned.m8n8.x4.shared.b16 {%0,%1,%2,%3}, [%4];" \
        : "=r"(d0), "=r"(d1), "=r"(d2), "=r"(d3) : "r"(a))

// ---------------------------------------------------------------------------
__global__ void init_kernel() {
    int t = blockIdx.x*blockDim.x + threadIdx.x;
    if (t < Edim) { g_counts[t] = 0; g_cursor[t] = 0; }
    for (int r = t; r < NR; r += gridDim.x*blockDim.x) g_row_token[r] = 0;
}

// x (fp32, [S][512]) -> Xhi/Xlo bf16
__global__ void conv_x_kernel(const float* __restrict__ x) {
    size_t i = (size_t)(blockIdx.x*blockDim.x + threadIdx.x);
    size_t n4 = (size_t)Stok*Mdim/4;
    for (; i < n4; i += (size_t)gridDim.x*blockDim.x) {
        float4 v = ((const float4*)x)[i];
        uint32_t h0, l0, h1, l1;
        split2(v.x, v.y, h0, l0);
        split2(v.z, v.w, h1, l1);
        ((uint32_t*)g_Xhi)[2*i]   = h0; ((uint32_t*)g_Xhi)[2*i+1] = h1;
        ((uint32_t*)g_Xlo)[2*i]   = l0; ((uint32_t*)g_Xlo)[2*i+1] = l1;
    }
}

// W[e][KD][ND] fp32 -> Wt[e][NP][KP] bf16 hi/lo (transposed, zero-padded)
template<int KD, int ND, int KP, int NP>
__global__ void conv_wt_kernel(const float* __restrict__ W,
                               __nv_bfloat16* __restrict__ Dh,
                               __nv_bfloat16* __restrict__ Dl) {
    __shared__ float tile[32][33];
    int e = blockIdx.z;
    int kb = blockIdx.x*32, nb = blockIdx.y*32;
    int tx = threadIdx.x, ty = threadIdx.y;
    int k = kb + ty, n = nb + tx;
    float v = 0.f;
    if (k < KD && n < ND) v = W[(size_t)e*KD*ND + (size_t)k*ND + n];
    tile[ty][tx] = v;
    __syncthreads();
    int k2 = kb + tx, n2 = nb + ty;
    float u = tile[tx][ty];
    __nv_bfloat16 h = __float2bfloat16(u);
    float r = u - __bfloat162float(h);
    size_t di = ((size_t)e*NP + n2)*KP + k2;
    Dh[di] = h;
    Dl[di] = __float2bfloat16(r);
}

__global__ void pad_bias_kernel(const float* __restrict__ src, float* __restrict__ dst,
                                int ND, int NP) {
    int i = blockIdx.x*blockDim.x + threadIdx.x;
    if (i >= Edim*NP) return;
    int e = i / NP, c = i % NP;
    dst[i] = (c < ND) ? src[e*ND + c] : 0.f;
}

__global__ void router_kernel(const float* __restrict__ x,
                              const float* __restrict__ noise,
                              const float* __restrict__ Wr,
                              float* __restrict__ out_sel) {
    __shared__ float sWr[Edim*Mdim];
    __shared__ float sP[8][Edim];
    int tid = threadIdx.x;
    for (int i = tid; i < Edim*Mdim; i += 256) sWr[i] = Wr[i];
    __syncthreads();

    int warp = tid >> 5, lane = tid & 31;
    int s = blockIdx.x*8 + warp;

    float p[Edim];
    #pragma unroll
    for (int e = 0; e < Edim; e++) p[e] = 0.f;
    const float* xr = x + (size_t)s*Mdim;
    for (int k = lane; k < Mdim; k += 32) {
        float xv = xr[k];
        #pragma unroll
        for (int e = 0; e < Edim; e++) p[e] += xv * sWr[e*Mdim + k];
    }
    #pragma unroll
    for (int e = 0; e < Edim; e++) {
        #pragma unroll
        for (int o = 16; o > 0; o >>= 1) p[e] += __shfl_xor_sync(0xffffffffu, p[e], o);
    }
    float mx = -1e30f;
    #pragma unroll
    for (int e = 0; e < Edim; e++) { p[e] += noise[(size_t)s*Edim + e]; mx = fmaxf(mx, p[e]); }
    float sum = 0.f;
    #pragma unroll
    for (int e = 0; e < Edim; e++) { p[e] = __expf(p[e]-mx); sum += p[e]; }
    float inv = 1.f/sum;
    #pragma unroll
    for (int e = 0; e < Edim; e++) p[e] *= inv;

    int e0 = 0; float v0 = p[0];
    #pragma unroll
    for (int e = 1; e < Edim; e++) if (p[e] > v0) { v0 = p[e]; e0 = e; }
    int e1 = -1; float v1 = -1.f;
    #pragma unroll
    for (int e = 0; e < Edim; e++) if (e != e0 && p[e] > v1) { v1 = p[e]; e1 = e; }
    float gs = v0 + v1;

    if (lane == 0) {
        g_topk[2*s]   = e0; g_topk[2*s+1] = e1;
        g_gate[2*s]   = v0/gs; g_gate[2*s+1] = v1/gs;
        atomicAdd(&g_counts[e0], 1);
        atomicAdd(&g_counts[e1], 1);
        #pragma unroll
        for (int e = 0; e < Edim; e++) sP[warp][e] = p[e];
    }
    if (lane < Edim)
        out_sel[(size_t)s*Edim + lane] = (lane == e0 || lane == e1) ? 1.f : 0.f;
    __syncthreads();
    if (tid < Edim) {
        float acc = 0.f;
        #pragma unroll
        for (int w = 0; w < 8; w++) acc += sP[w][tid];
        g_proxy_partial[(size_t)blockIdx.x*Edim + tid] = acc;
    }
}

__global__ void loss_kernel(float* __restrict__ out_loss) {
    __shared__ float sp[Edim];
    int e = threadIdx.x;
    if (e < Edim) {
        float acc = 0.f;
        for (int b = 0; b < RBLOCKS; b++) acc += g_proxy_partial[(size_t)b*Edim + e];
        sp[e] = acc;
    }
    __syncthreads();
    if (e == 0) {
        float l = 0.f;
        for (int i = 0; i < Edim; i++) l += sp[i] * (float)g_counts[i];
        out_loss[0] = l * (float)Edim / ((float)Stok * (float)Stok);
        out_loss[1] = 0.f;
    }
}

__global__ void build_tiles_kernel() {
    int off = 0, nt = 0;
    for (int e = 0; e < Edim; e++) {
        g_offsets[e] = off;
        int c = g_counts[e];
        int ct = (c + TM - 1)/TM;
        for (int t = 0; t < ct; t++) { g_tile_expert[nt] = e; g_tile_row0[nt] = off + t*TM; nt++; }
        off += ct*TM;
    }
    g_n_tiles = nt;
}

__global__ void scatter_kernel() {
    int s = blockIdx.x*blockDim.x + threadIdx.x;
    if (s >= Stok) return;
    #pragma unroll
    for (int k = 0; k < 2; k++) {
        int e = g_topk[2*s+k];
        int pos = atomicAdd(&g_cursor[e], 1);
        int r = g_offsets[e] + pos;
        g_row_token[r] = s;
        g_token_rows[2*s+k] = r;
    }
}

// ---------------------------------------------------------------------------
// HMMA grouped GEMM on precomputed bf16 hi/lo operands.
// CTA 128x128, 256 thr, warp tile 64x32, K-chunk 32. Producers: pure copies.
// Frag loads via ldmatrix.x4. Smem rows = 32 halves (4x16B groups), XOR swizzle
// by ((row>>1)&3). Per buffer: Ah 8K | Al 8K | Bh 8K | Bl 8K = 32KB, x2 = 64KB.
#define GBUF 32768
#define SMEM_MM (2*GBUF)

template<int KP, int NP, bool RELU, bool GATHER, bool OUT_BF>
__global__ void __launch_bounds__(256, 2)
expert_gemm_bf(const __nv_bfloat16* __restrict__ Ahi, const __nv_bfloat16* __restrict__ Alo,
               const __nv_bfloat16* __restrict__ Whi, const __nv_bfloat16* __restrict__ Wlo,
               const float* __restrict__ biasp,
               __nv_bfloat16* __restrict__ Yhi, __nv_bfloat16* __restrict__ Ylo,
               float* __restrict__ Yf) {
    int tile = blockIdx.x;
    if (tile >= g_n_tiles) return;
    int row0 = g_tile_row0[tile];
    int e    = g_tile_expert[tile];
    int nb   = blockIdx.y * 128;
    const float* be = biasp + e*NP + nb;

    extern __shared__ char smem[];
    uint32_t sbase = smem_u32(smem);
    int tid = threadIdx.x, wid = tid >> 5, lane = tid & 31;
    int g = lane >> 2, tig = lane & 3;
    int m0 = (wid & 1) * 64, n0 = (wid >> 1) * 32;

    // ---- producer geometry ----
    int am = tid >> 1, akh = (tid & 1) * 16;          // A: row, k-half (16 halves)
    int ag0 = (tid & 1) * 2;
    int asw = (am >> 1) & 3;
    int ar = GATHER ? g_row_token[row0 + am] : (row0 + am);
    size_t abase = (size_t)ar*KP + akh;
    int bn = tid & 127, bkg = tid >> 7;               // B: n-row, k-group (16 halves)
    int bg0 = bkg * 2;
    int bsw = (bn >> 1) & 3;
    size_t wbase = ((size_t)e*NP + (nb + bn))*KP + bkg*16;

    // ---- ldmatrix lane geometry ----
    int rA  = m0 + (lane & 7) + 8*((lane >> 3) & 1);
    int kgA = (lane >> 4) & 1;
    int swA = (rA >> 1) & 3;
    uint32_t rA0 = (uint32_t)rA * 64;
    uint32_t aoff0 = (uint32_t)((kgA ^ swA) << 4);
    uint32_t aoff1 = (uint32_t)(((2 + kgA) ^ swA) << 4);
    int rB  = n0 + 8*((lane >> 4) & 1) + (lane & 7);
    int kgB = (lane >> 3) & 1;
    int swB = (rB >> 1) & 3;
    uint32_t rB0 = (uint32_t)rB * 64;
    uint32_t boff0 = (uint32_t)((kgB ^ swB) << 4);
    uint32_t boff1 = (uint32_t)(((2 + kgB) ^ swB) << 4);

    const int NCH = KP / 32;

    float acc[4][4][4];
    #pragma unroll
    for (int i = 0; i < 4; i++)
        #pragma unroll
        for (int j = 0; j < 4; j++)
            #pragma unroll
            for (int c = 0; c < 4; c++) acc[i][j][c] = 0.f;

    uint4 sAh0, sAh1, sAl0, sAl1, sBh0, sBh1, sBl0, sBl1;

    auto load_chunk = [&](int ch) {
        size_t k0 = (size_t)ch * 32;
        const uint4* pAh = (const uint4*)(Ahi + abase + k0);
        const uint4* pAl = (const uint4*)(Alo + abase + k0);
        sAh0 = pAh[0]; sAh1 = pAh[1];
        sAl0 = pAl[0]; sAl1 = pAl[1];
        const uint4* pBh = (const uint4*)(Whi + wbase + k0);
        const uint4* pBl = (const uint4*)(Wlo + wbase + k0);
        sBh0 = pBh[0]; sBh1 = pBh[1];
        sBl0 = pBl[0]; sBl1 = pBl[1];
    };

    auto store_chunk = [&](int b) {
        char* buf = smem + b*GBUF;
        char* Ah = buf;         char* Al = buf + 8192;
        char* Bh = buf + 16384; char* Bl = buf + 24576;
        *(uint4*)(Ah + am*64 + (((ag0  ) ^ asw) << 4)) = sAh0;
        *(uint4*)(Ah + am*64 + (((ag0+1) ^ asw) << 4)) = sAh1;
        *(uint4*)(Al + am*64 + (((ag0  ) ^ asw) << 4)) = sAl0;
        *(uint4*)(Al + am*64 + (((ag0+1) ^ asw) << 4)) = sAl1;
        *(uint4*)(Bh + bn*64 + (((bg0  ) ^ bsw) << 4)) = sBh0;
        *(uint4*)(Bh + bn*64 + (((bg0+1) ^ bsw) << 4)) = sBh1;
        *(uint4*)(Bl + bn*64 + (((bg0  ) ^ bsw) << 4)) = sBl0;
        *(uint4*)(Bl + bn*64 + (((bg0+1) ^ bsw) << 4)) = sBl1;
    };

    auto compute = [&](int b) {
        uint32_t Ah = sbase + b*GBUF;
        uint32_t Al = Ah + 8192, Bh = Ah + 16384, Bl = Ah + 24576;
        #pragma unroll
        for (int ks = 0; ks < 2; ks++) {
            uint32_t bo = ks ? boff1 : boff0;
            uint32_t ao = ks ? aoff1 : aoff0;
            uint32_t bh[4][2], bl[4][2];
            LDSM4(bh[0][0], bh[0][1], bh[1][0], bh[1][1], Bh + rB0 + bo);
            LDSM4(bh[2][0], bh[2][1], bh[3][0], bh[3][1], Bh + rB0 + 1024 + bo);
            LDSM4(bl[0][0], bl[0][1], bl[1][0], bl[1][1], Bl + rB0 + bo);
            LDSM4(bl[2][0], bl[2][1], bl[3][0], bl[3][1], Bl + rB0 + 1024 + bo);
            #pragma unroll
            for (int mf = 0; mf < 4; mf++) {
                uint32_t ah[4], al[4];
                LDSM4(ah[0], ah[1], ah[2], ah[3], Ah + rA0 + mf*1024 + ao);
                LDSM4(al[0], al[1], al[2], al[3], Al + rA0 + mf*1024 + ao);
                #pragma unroll
                for (int nf = 0; nf < 4; nf++) {
                    MMA4(acc[mf][nf], ah, bh[nf]);
                    MMA4(acc[mf][nf], ah, bl[nf]);
                    MMA4(acc[mf][nf], al, bh[nf]);
                }
            }
        }
    };

    load_chunk(0);
    store_chunk(0);
    __syncthreads();
    for (int ch = 0; ch < NCH; ch++) {
        if (ch + 1 < NCH) load_chunk(ch + 1);
        compute(ch & 1);
        if (ch + 1 < NCH) store_chunk((ch + 1) & 1);
        __syncthreads();
    }

    // epilogue: 64x32 warp tile; two rows (r, r+8) per frag
    #pragma unroll
    for (int mf = 0; mf < 4; mf++) {
        int r0 = row0 + m0 + 16*mf + g;
        #pragma unroll
        for (int nf = 0; nf < 4; nf++) {
            int co = n0 + 8*nf + 2*tig;          // col offset within 128-tile
            float b0 = be[co], b1 = be[co+1];
            float v0 = acc[mf][nf][0] + b0;
            float v1 = acc[mf][nf][1] + b1;
            float v2 = acc[mf][nf][2] + b0;
            float v3 = acc[mf][nf][3] + b1;
            if (RELU) {
                v0 = fmaxf(v0, 0.f); v1 = fmaxf(v1, 0.f);
                v2 = fmaxf(v2, 0.f); v3 = fmaxf(v3, 0.f);
            }
            int cc = nb + co;
            if (OUT_BF) {
                uint32_t h0, l0, h1, l1;
                split2(v0, v1, h0, l0);
                split2(v2, v3, h1, l1);
                *(uint32_t*)(Yhi + (size_t)r0*NP + cc)     = h0;
                *(uint32_t*)(Ylo + (size_t)r0*NP + cc)     = l0;
                *(uint32_t*)(Yhi + (size_t)(r0+8)*NP + cc) = h1;
                *(uint32_t*)(Ylo + (size_t)(r0+8)*NP + cc) = l1;
            } else {
                *(float2*)(Yf + (size_t)r0*NP + cc)     = make_float2(v0, v1);
                *(float2*)(Yf + (size_t)(r0+8)*NP + cc) = make_float2(v2, v3);
            }
        }
    }
}

__global__ void combine_kernel(float* __restrict__ out) {
    int s = blockIdx.x;
    int d = threadIdx.x;
    int r0 = g_token_rows[2*s], r1 = g_token_rows[2*s+1];
    float g0 = g_gate[2*s], g1 = g_gate[2*s+1];
    out[(size_t)s*Ddim + d] = g0*g_A4[(size_t)r0*NP4 + d] + g1*g_A4[(size_t)r1*NP4 + d];
}

// ---------------------------------------------------------------------------
extern "C" void kernel_launch(void* const* d_in, const int* in_sizes, int n_in,
                              void* d_out, int out_size) {
    (void)in_sizes; (void)n_in; (void)out_size;
    const float* x     = (const float*)d_in[0];
    const float* noise = (const float*)d_in[1];
    const float* Wr    = (const float*)d_in[2];
    const float* W1    = (const float*)d_in[3];
    const float* b1    = (const float*)d_in[4];
    const float* W2    = (const float*)d_in[5];
    const float* b2    = (const float*)d_in[6];
    const float* W3    = (const float*)d_in[7];
    const float* b3    = (const float*)d_in[8];
    const float* W4    = (const float*)d_in[9];
    const float* b4    = (const float*)d_in[10];

    float* out       = (float*)d_out;
    float* out_final = out;
    float* out_sel   = out + (size_t)Stok*Ddim;
    float* out_loss  = out_sel + (size_t)Stok*Edim;

    // symbol addresses (host-side queries; capture-safe)
    void *pXh, *pXl, *pA1h, *pA1l, *pA2h, *pA2l, *pA3h, *pA3l, *pA4;
    void *pW1h, *pW1l, *pW2h, *pW2l, *pW3h, *pW3l, *pW4h, *pW4l;
    void *pB1, *pB2, *pB3, *pB4;
    cudaGetSymbolAddress(&pXh, g_Xhi);   cudaGetSymbolAddress(&pXl, g_Xlo);
    cudaGetSymbolAddress(&pA1h, g_A1h);  cudaGetSymbolAddress(&pA1l, g_A1l);
    cudaGetSymbolAddress(&pA2h, g_A2h);  cudaGetSymbolAddress(&pA2l, g_A2l);
    cudaGetSymbolAddress(&pA3h, g_A3h);  cudaGetSymbolAddress(&pA3l, g_A3l);
    cudaGetSymbolAddress(&pA4, g_A4);
    cudaGetSymbolAddress(&pW1h, g_W1h);  cudaGetSymbolAddress(&pW1l, g_W1l);
    cudaGetSymbolAddress(&pW2h, g_W2h);  cudaGetSymbolAddress(&pW2l, g_W2l);
    cudaGetSymbolAddress(&pW3h, g_W3h);  cudaGetSymbolAddress(&pW3l, g_W3l);
    cudaGetSymbolAddress(&pW4h, g_W4h);  cudaGetSymbolAddress(&pW4l, g_W4l);
    cudaGetSymbolAddress(&pB1, g_b1p);   cudaGetSymbolAddress(&pB2, g_b2p);
    cudaGetSymbolAddress(&pB3, g_b3p);   cudaGetSymbolAddress(&pB4, g_b4p);

    cudaFuncSetAttribute(expert_gemm_bf<KP1, NP1, true,  true,  true >, cudaFuncAttributeMaxDynamicSharedMemorySize, SMEM_MM);
    cudaFuncSetAttribute(expert_gemm_bf<KP2, NP2, true,  false, true >, cudaFuncAttributeMaxDynamicSharedMemorySize, SMEM_MM);
    cudaFuncSetAttribute(expert_gemm_bf<KP3, NP3, true,  false, true >, cudaFuncAttributeMaxDynamicSharedMemorySize, SMEM_MM);
    cudaFuncSetAttribute(expert_gemm_bf<KP4, NP4, false, false, false>, cudaFuncAttributeMaxDynamicSharedMemorySize, SMEM_MM);

    init_kernel<<<148, 256>>>();
    conv_x_kernel<<<2048, 256>>>(x);
    conv_wt_kernel<Mdim, H1d, KP1, NP1><<<dim3(KP1/32, NP1/32, Edim), dim3(32,32)>>>(W1, (__nv_bfloat16*)pW1h, (__nv_bfloat16*)pW1l);
    conv_wt_kernel<H1d,  H2d, KP2, NP2><<<dim3(KP2/32, NP2/32, Edim), dim3(32,32)>>>(W2, (__nv_bfloat16*)pW2h, (__nv_bfloat16*)pW2l);
    conv_wt_kernel<H2d,  H3d, KP3, NP3><<<dim3(KP3/32, NP3/32, Edim), dim3(32,32)>>>(W3, (__nv_bfloat16*)pW3h, (__nv_bfloat16*)pW3l);
    conv_wt_kernel<H3d,  Ddim,KP4, NP4><<<dim3(KP4/32, NP4/32, Edim), dim3(32,32)>>>(W4, (__nv_bfloat16*)pW4h, (__nv_bfloat16*)pW4l);
    pad_bias_kernel<<<(Edim*NP1+255)/256, 256>>>(b1, (float*)pB1, H1d, NP1);
    pad_bias_kernel<<<(Edim*NP2+255)/256, 256>>>(b2, (float*)pB2, H2d, NP2);
    pad_bias_kernel<<<(Edim*NP3+255)/256, 256>>>(b3, (float*)pB3, H3d, NP3);
    pad_bias_kernel<<<(Edim*NP4+255)/256, 256>>>(b4, (float*)pB4, Ddim, NP4);

    router_kernel<<<RBLOCKS, 256>>>(x, noise, Wr, out_sel);
    loss_kernel<<<1, 32>>>(out_loss);
    build_tiles_kernel<<<1, 1>>>();
    scatter_kernel<<<Stok/256, 256>>>();

    expert_gemm_bf<KP1, NP1, true,  true,  true ><<<dim3(NT_MAX, NP1/128), 256, SMEM_MM>>>(
        (const __nv_bfloat16*)pXh, (const __nv_bfloat16*)pXl,
        (const __nv_bfloat16*)pW1h, (const __nv_bfloat16*)pW1l, (const float*)pB1,
        (__nv_bfloat16*)pA1h, (__nv_bfloat16*)pA1l, nullptr);
    expert_gemm_bf<KP2, NP2, true,  false, true ><<<dim3(NT_MAX, NP2/128), 256, SMEM_MM>>>(
        (const __nv_bfloat16*)pA1h, (const __nv_bfloat16*)pA1l,
        (const __nv_bfloat16*)pW2h, (const __nv_bfloat16*)pW2l, (const float*)pB2,
        (__nv_bfloat16*)pA2h, (__nv_bfloat16*)pA2l, nullptr);
    expert_gemm_bf<KP3, NP3, true,  false, true ><<<dim3(NT_MAX, NP3/128), 256, SMEM_MM>>>(
        (const __nv_bfloat16*)pA2h, (const __nv_bfloat16*)pA2l,
        (const __nv_bfloat16*)pW3h, (const __nv_bfloat16*)pW3l, (const float*)pB3,
        (__nv_bfloat16*)pA3h, (__nv_bfloat16*)pA3l, nullptr);
    expert_gemm_bf<KP4, NP4, false, false, false><<<dim3(NT_MAX, NP4/128), 256, SMEM_MM>>>(
        (const __nv_bfloat16*)pA3h, (const __nv_bfloat16*)pA3l,
        (const __nv_bfloat16*)pW4h, (const __nv_bfloat16*)pW4l, (const float*)pB4,
        nullptr, nullptr, (float*)pA4);

    combine_kernel<<<Stok, Ddim>>>(out_final);
}